// round 15
// baseline (speedup 1.0000x reference)
#include <cuda_runtime.h>

#define DIM   4096
#define RANK  32
#define NEDIT 32            // B(4) * 8 edited rows

// asm-pinned vector load/store: volatile asm preserves program order, so all
// 4 loads issue before any store — MLP=4 guaranteed at ANY register budget.
#define LDG4(v, p) asm volatile("ld.global.v4.f32 {%0,%1,%2,%3}, [%4];" \
    : "=f"((v).x), "=f"((v).y), "=f"((v).z), "=f"((v).w) : "l"(p))
#define STG4(p, v) asm volatile("st.global.v4.f32 [%0], {%1,%2,%3,%4};" \
    :: "l"(p), "f"((v).x), "f"((v).y), "f"((v).z), "f"((v).w) : "memory")

// ---------------------------------------------------------------------------
// Single kernel, two CTA roles:
//   bids 0..31      : self-contained per-row ReFT edit (hidden in copy wave)
//   bids 32..16415  : ONE row per CTA, asm-pinned 4x(LDG.128) then 4x(STG.128)
// __launch_bounds__(256, 8): 32-reg ceiling -> 8 CTAs/SM for copy CTAs
// (standalone-copy occupancy) while asm guarantees the load batch.
// ---------------------------------------------------------------------------
__global__ __launch_bounds__(256, 8) void reft_kernel(
    const float* __restrict__ hs,
    const float* __restrict__ Wsrc_p, const float* __restrict__ bsrc_p,
    const float* __restrict__ Wproj_p,
    const float* __restrict__ Wsrc_s, const float* __restrict__ bsrc_s,
    const float* __restrict__ Wproj_s,
    const int* __restrict__ offsets, const int* __restrict__ seqlens,
    float* __restrict__ out)
{
    const int tid = threadIdx.x;

    if (blockIdx.x >= NEDIT) {
        // ---------------- copy path: one row per CTA ----------------
        const int row = blockIdx.x - NEDIT;    // 0..16383
        const int b = row >> 12;
        const int t = row & 4095;
        const int off = offsets[b];
        const int seq = seqlens[b];
        if (((unsigned)(t - off) < 4u) | ((unsigned)(t - (off + seq - 4)) < 4u))
            return;   // edited row: owned by an edit CTA

        const long base = (long)row * DIM;
        const float4* x4 = (const float4*)(hs + base) + tid;
        float4*       o4 = (float4*)(out + base) + tid;
        float4 v0, v1, v2, v3;
        LDG4(v0, x4);
        LDG4(v1, x4 + 256);
        LDG4(v2, x4 + 512);
        LDG4(v3, x4 + 768);
        STG4(o4,       v0);
        STG4(o4 + 256, v1);
        STG4(o4 + 512, v2);
        STG4(o4 + 768, v3);
        return;
    }

    // ---------------- edit path: one CTA per edited row --------------------
    __shared__ float4 xs4[DIM / 4];  // 16 KB
    __shared__ float  dots[2 * RANK];
    __shared__ float  s[RANK];

    const int j = blockIdx.x;        // 0..31
    const int b = j >> 3;
    const int slot = j & 7;
    int pos;
    const float *Wsrc, *bias, *Wproj;
    if (slot < 4) {
        pos = offsets[b] + slot;
        Wsrc = Wsrc_p; bias = bsrc_p; Wproj = Wproj_p;
    } else {
        pos = offsets[b] + seqlens[b] - 8 + slot;
        Wsrc = Wsrc_s; bias = bsrc_s; Wproj = Wproj_s;
    }

    const long base = ((long)b * 4096 + pos) * DIM;
    const float4* x4 = (const float4*)(hs + base);
    #pragma unroll
    for (int k = 0; k < 4; k++) {
        int i = tid + k * 256;
        xs4[i] = x4[i];
    }
    __syncthreads();

    // 64 dots: 8 warps x 8 dots, single accumulator (low reg pressure)
    const int warp = tid >> 5;
    const int lane = tid & 31;
    #pragma unroll
    for (int k = 0; k < 8; k++) {
        const int di = warp * 8 + k;       // 0..63
        const float4* W4 = (const float4*)((di < RANK)
                               ? (Wsrc  + (long)di * DIM)
                               : (Wproj + (long)(di - RANK) * DIM));
        float acc = 0.f;
        #pragma unroll 4
        for (int i = lane; i < DIM / 4; i += 32) {
            float4 w  = W4[i];
            float4 xv = xs4[i];
            acc += w.x * xv.x + w.y * xv.y + w.z * xv.z + w.w * xv.w;
        }
        #pragma unroll
        for (int o = 16; o > 0; o >>= 1)
            acc += __shfl_xor_sync(0xffffffff, acc, o);
        if (lane == 0) dots[di] = acc;
    }
    __syncthreads();

    if (tid < RANK) {
        float src  = dots[tid] + bias[tid];
        float proj = dots[tid + RANK];
        s[tid] = (src > 0.f ? src : 0.f) - proj;
    }
    __syncthreads();

    float4* o4 = (float4*)(out + base);
    #pragma unroll
    for (int k = 0; k < 4; k++) {
        int i = tid + k * 256;
        float4 acc = xs4[i];
        #pragma unroll
        for (int r = 0; r < RANK; r++) {
            float4 w = ((const float4*)(Wproj + (long)r * DIM))[i];
            float sr = s[r];
            acc.x += sr * w.x;
            acc.y += sr * w.y;
            acc.z += sr * w.z;
            acc.w += sr * w.w;
        }
        o4[i] = acc;
    }
}

extern "C" void kernel_launch(void* const* d_in, const int* in_sizes, int n_in,
                              void* d_out, int out_size) {
    const float* hs      = (const float*)d_in[0];
    const float* Wsrc_p  = (const float*)d_in[1];
    const float* bsrc_p  = (const float*)d_in[2];
    const float* Wproj_p = (const float*)d_in[3];
    const float* Wsrc_s  = (const float*)d_in[4];
    const float* bsrc_s  = (const float*)d_in[5];
    const float* Wproj_s = (const float*)d_in[6];
    const int*   offsets = (const int*)d_in[7];
    const int*   seqlens = (const int*)d_in[8];
    float* out = (float*)d_out;

    const int nrows = out_size / DIM;      // 16384
    reft_kernel<<<NEDIT + nrows, 256>>>(
        hs, Wsrc_p, bsrc_p, Wproj_p, Wsrc_s, bsrc_s, Wproj_s,
        offsets, seqlens, out);
}

// round 16
// speedup vs baseline: 1.5380x; 1.5380x over previous
#include <cuda_runtime.h>

#define DIM   4096
#define RANK  32
#define NEDIT 32            // B(4) * 8 edited rows
#define NCOPY 8192          // copy CTAs: 2 rows each

// ---------------------------------------------------------------------------
// Single kernel, two CTA roles:
//   bids 0..31          : self-contained per-row ReFT edit (hidden in wave)
//   bids 32..32+8191    : TWO rows per CTA, 8-deep float4 load batch
// __launch_bounds__(256, 2): regs=128 ceiling (R13-proven to preserve
// compiler load batching); 8 float4 = 32 data regs fits easily.
// ---------------------------------------------------------------------------
__global__ __launch_bounds__(256, 2) void reft_kernel(
    const float* __restrict__ hs,
    const float* __restrict__ Wsrc_p, const float* __restrict__ bsrc_p,
    const float* __restrict__ Wproj_p,
    const float* __restrict__ Wsrc_s, const float* __restrict__ bsrc_s,
    const float* __restrict__ Wproj_s,
    const int* __restrict__ offsets, const int* __restrict__ seqlens,
    float* __restrict__ out)
{
    const int tid = threadIdx.x;

    if (blockIdx.x >= NEDIT) {
        // ------------- copy path: two consecutive rows per CTA -------------
        const int cbid = blockIdx.x - NEDIT;   // 0..8191
        const int row0 = cbid * 2;             // rows row0, row0+1 (same batch)
        const int b = row0 >> 12;
        const int t0 = row0 & 4095;
        const int t1 = t0 + 1;
        const int off = offsets[b];
        const int ss  = off + seqlens[b] - 4;
        const bool e0 = ((unsigned)(t0 - off) < 4u) | ((unsigned)(t0 - ss) < 4u);
        const bool e1 = ((unsigned)(t1 - off) < 4u) | ((unsigned)(t1 - ss) < 4u);

        const long base0 = (long)row0 * DIM;
        const float4* xa = (const float4*)(hs + base0) + tid;
        const float4* xb = xa + (DIM / 4);
        float4*       oa = (float4*)(out + base0) + tid;
        float4*       ob = oa + (DIM / 4);

        // 8-deep load batch (straight-line; compiler schedules at regs<=128)
        float4 a0 = xa[0],   a1 = xa[256], a2 = xa[512], a3 = xa[768];
        float4 b0 = xb[0],   b1 = xb[256], b2 = xb[512], b3 = xb[768];
        if (!e0) {
            oa[0]   = a0;
            oa[256] = a1;
            oa[512] = a2;
            oa[768] = a3;
        }
        if (!e1) {
            ob[0]   = b0;
            ob[256] = b1;
            ob[512] = b2;
            ob[768] = b3;
        }
        return;
    }

    // ---------------- edit path: one CTA per edited row (R13) --------------
    __shared__ float4 xs4[DIM / 4];  // 16 KB
    __shared__ float  dots[2 * RANK];
    __shared__ float  s[RANK];

    const int j = blockIdx.x;        // 0..31
    const int b = j >> 3;
    const int slot = j & 7;
    int pos;
    const float *Wsrc, *bias, *Wproj;
    if (slot < 4) {
        pos = offsets[b] + slot;
        Wsrc = Wsrc_p; bias = bsrc_p; Wproj = Wproj_p;
    } else {
        pos = offsets[b] + seqlens[b] - 8 + slot;
        Wsrc = Wsrc_s; bias = bsrc_s; Wproj = Wproj_s;
    }

    const long base = ((long)b * 4096 + pos) * DIM;
    const float4* x4 = (const float4*)(hs + base);
    #pragma unroll
    for (int k = 0; k < 4; k++) {
        int i = tid + k * 256;
        xs4[i] = x4[i];
    }
    __syncthreads();

    const int warp = tid >> 5;
    const int lane = tid & 31;
    #pragma unroll
    for (int k = 0; k < 8; k++) {
        const int di = warp * 8 + k;       // 0..63
        const float4* W4 = (const float4*)((di < RANK)
                               ? (Wsrc  + (long)di * DIM)
                               : (Wproj + (long)(di - RANK) * DIM));
        float acc0 = 0.f, acc1 = 0.f;
        #pragma unroll 4
        for (int i = lane; i < DIM / 4; i += 64) {
            float4 w0 = W4[i],      xv0 = xs4[i];
            float4 w1 = W4[i + 32], xv1 = xs4[i + 32];
            acc0 += w0.x * xv0.x + w0.y * xv0.y + w0.z * xv0.z + w0.w * xv0.w;
            acc1 += w1.x * xv1.x + w1.y * xv1.y + w1.z * xv1.z + w1.w * xv1.w;
        }
        float acc = acc0 + acc1;
        #pragma unroll
        for (int o = 16; o > 0; o >>= 1)
            acc += __shfl_xor_sync(0xffffffff, acc, o);
        if (lane == 0) dots[di] = acc;
    }
    __syncthreads();

    if (tid < RANK) {
        float src  = dots[tid] + bias[tid];
        float proj = dots[tid + RANK];
        s[tid] = (src > 0.f ? src : 0.f) - proj;
    }
    __syncthreads();

    float4* o4 = (float4*)(out + base);
    #pragma unroll
    for (int k = 0; k < 4; k++) {
        int i = tid + k * 256;
        float4 acc = xs4[i];
        #pragma unroll
        for (int r = 0; r < RANK; r++) {
            float4 w = ((const float4*)(Wproj + (long)r * DIM))[i];
            float sr = s[r];
            acc.x += sr * w.x;
            acc.y += sr * w.y;
            acc.z += sr * w.z;
            acc.w += sr * w.w;
        }
        o4[i] = acc;
    }
}

extern "C" void kernel_launch(void* const* d_in, const int* in_sizes, int n_in,
                              void* d_out, int out_size) {
    const float* hs      = (const float*)d_in[0];
    const float* Wsrc_p  = (const float*)d_in[1];
    const float* bsrc_p  = (const float*)d_in[2];
    const float* Wproj_p = (const float*)d_in[3];
    const float* Wsrc_s  = (const float*)d_in[4];
    const float* bsrc_s  = (const float*)d_in[5];
    const float* Wproj_s = (const float*)d_in[6];
    const int*   offsets = (const int*)d_in[7];
    const int*   seqlens = (const int*)d_in[8];
    float* out = (float*)d_out;

    reft_kernel<<<NEDIT + NCOPY, 256>>>(
        hs, Wsrc_p, bsrc_p, Wproj_p, Wsrc_s, bsrc_s, Wproj_s,
        offsets, seqlens, out);
}

// round 17
// speedup vs baseline: 1.6909x; 1.0994x over previous
#include <cuda_runtime.h>

#define DIM   4096
#define RANK  32
#define NEDIT 32            // B(4) * 8 edited rows
#define ROWS_PER_CTA 4
#define NCOPY (16384 / ROWS_PER_CTA)   // 4096 copy CTAs

// ---------------------------------------------------------------------------
// Single kernel, two CTA roles:
//   bids 0..31        : self-contained per-row ReFT edit (hidden in wave)
//   bids 32..32+4095  : FOUR rows per CTA, 16-deep float4 load batch
// __launch_bounds__(256, 2): regs=128 ceiling (R13/R16-proven to preserve
// compiler load batching). 16 float4 = 64 data regs fits the budget.
// ---------------------------------------------------------------------------
__global__ __launch_bounds__(256, 2) void reft_kernel(
    const float* __restrict__ hs,
    const float* __restrict__ Wsrc_p, const float* __restrict__ bsrc_p,
    const float* __restrict__ Wproj_p,
    const float* __restrict__ Wsrc_s, const float* __restrict__ bsrc_s,
    const float* __restrict__ Wproj_s,
    const int* __restrict__ offsets, const int* __restrict__ seqlens,
    float* __restrict__ out)
{
    const int tid = threadIdx.x;

    if (blockIdx.x >= NEDIT) {
        // ------------- copy path: four consecutive rows per CTA ------------
        const int cbid = blockIdx.x - NEDIT;   // 0..4095
        const int row0 = cbid * ROWS_PER_CTA;  // all 4 rows share batch b
        const int b = row0 >> 12;
        const int t0 = row0 & 4095;
        const int off = offsets[b];
        const int ss  = off + seqlens[b] - 4;
        const bool e0 = ((unsigned)(t0     - off) < 4u) | ((unsigned)(t0     - ss) < 4u);
        const bool e1 = ((unsigned)(t0 + 1 - off) < 4u) | ((unsigned)(t0 + 1 - ss) < 4u);
        const bool e2 = ((unsigned)(t0 + 2 - off) < 4u) | ((unsigned)(t0 + 2 - ss) < 4u);
        const bool e3 = ((unsigned)(t0 + 3 - off) < 4u) | ((unsigned)(t0 + 3 - ss) < 4u);

        const long base0 = (long)row0 * DIM;
        const float4* xa = (const float4*)(hs + base0) + tid;
        const float4* xb = xa + (DIM / 4);
        const float4* xc = xb + (DIM / 4);
        const float4* xd = xc + (DIM / 4);
        float4* oa = (float4*)(out + base0) + tid;
        float4* ob = oa + (DIM / 4);
        float4* oc = ob + (DIM / 4);
        float4* od = oc + (DIM / 4);

        // 16-deep load batch (straight-line; compiler schedules at regs<=128)
        float4 a0 = xa[0], a1 = xa[256], a2 = xa[512], a3 = xa[768];
        float4 b0 = xb[0], b1 = xb[256], b2 = xb[512], b3 = xb[768];
        float4 c0 = xc[0], c1 = xc[256], c2 = xc[512], c3 = xc[768];
        float4 d0 = xd[0], d1 = xd[256], d2 = xd[512], d3 = xd[768];
        if (!e0) { oa[0] = a0; oa[256] = a1; oa[512] = a2; oa[768] = a3; }
        if (!e1) { ob[0] = b0; ob[256] = b1; ob[512] = b2; ob[768] = b3; }
        if (!e2) { oc[0] = c0; oc[256] = c1; oc[512] = c2; oc[768] = c3; }
        if (!e3) { od[0] = d0; od[256] = d1; od[512] = d2; od[768] = d3; }
        return;
    }

    // ---------------- edit path: one CTA per edited row (R13) --------------
    __shared__ float4 xs4[DIM / 4];  // 16 KB
    __shared__ float  dots[2 * RANK];
    __shared__ float  s[RANK];

    const int j = blockIdx.x;        // 0..31
    const int b = j >> 3;
    const int slot = j & 7;
    int pos;
    const float *Wsrc, *bias, *Wproj;
    if (slot < 4) {
        pos = offsets[b] + slot;
        Wsrc = Wsrc_p; bias = bsrc_p; Wproj = Wproj_p;
    } else {
        pos = offsets[b] + seqlens[b] - 8 + slot;
        Wsrc = Wsrc_s; bias = bsrc_s; Wproj = Wproj_s;
    }

    const long base = ((long)b * 4096 + pos) * DIM;
    const float4* x4 = (const float4*)(hs + base);
    #pragma unroll
    for (int k = 0; k < 4; k++) {
        int i = tid + k * 256;
        xs4[i] = x4[i];
    }
    __syncthreads();

    const int warp = tid >> 5;
    const int lane = tid & 31;
    #pragma unroll
    for (int k = 0; k < 8; k++) {
        const int di = warp * 8 + k;       // 0..63
        const float4* W4 = (const float4*)((di < RANK)
                               ? (Wsrc  + (long)di * DIM)
                               : (Wproj + (long)(di - RANK) * DIM));
        float acc0 = 0.f, acc1 = 0.f;
        #pragma unroll 4
        for (int i = lane; i < DIM / 4; i += 64) {
            float4 w0 = W4[i],      xv0 = xs4[i];
            float4 w1 = W4[i + 32], xv1 = xs4[i + 32];
            acc0 += w0.x * xv0.x + w0.y * xv0.y + w0.z * xv0.z + w0.w * xv0.w;
            acc1 += w1.x * xv1.x + w1.y * xv1.y + w1.z * xv1.z + w1.w * xv1.w;
        }
        float acc = acc0 + acc1;
        #pragma unroll
        for (int o = 16; o > 0; o >>= 1)
            acc += __shfl_xor_sync(0xffffffff, acc, o);
        if (lane == 0) dots[di] = acc;
    }
    __syncthreads();

    if (tid < RANK) {
        float src  = dots[tid] + bias[tid];
        float proj = dots[tid + RANK];
        s[tid] = (src > 0.f ? src : 0.f) - proj;
    }
    __syncthreads();

    float4* o4 = (float4*)(out + base);
    #pragma unroll
    for (int k = 0; k < 4; k++) {
        int i = tid + k * 256;
        float4 acc = xs4[i];
        #pragma unroll
        for (int r = 0; r < RANK; r++) {
            float4 w = ((const float4*)(Wproj + (long)r * DIM))[i];
            float sr = s[r];
            acc.x += sr * w.x;
            acc.y += sr * w.y;
            acc.z += sr * w.z;
            acc.w += sr * w.w;
        }
        o4[i] = acc;
    }
}

extern "C" void kernel_launch(void* const* d_in, const int* in_sizes, int n_in,
                              void* d_out, int out_size) {
    const float* hs      = (const float*)d_in[0];
    const float* Wsrc_p  = (const float*)d_in[1];
    const float* bsrc_p  = (const float*)d_in[2];
    const float* Wproj_p = (const float*)d_in[3];
    const float* Wsrc_s  = (const float*)d_in[4];
    const float* bsrc_s  = (const float*)d_in[5];
    const float* Wproj_s = (const float*)d_in[6];
    const int*   offsets = (const int*)d_in[7];
    const int*   seqlens = (const int*)d_in[8];
    float* out = (float*)d_out;

    reft_kernel<<<NEDIT + NCOPY, 256>>>(
        hs, Wsrc_p, bsrc_p, Wproj_p, Wsrc_s, bsrc_s, Wproj_s,
        offsets, seqlens, out);
}